// round 2
// baseline (speedup 1.0000x reference)
#include <cuda_runtime.h>
#include <cstdint>
#include <math.h>

// Problem constants
#define HDIM 512
#define G4   2048   // 4*H
#define EDIM 256
#define N_SC 640
#define T_SC 128
#define N_CM 640
#define T_CM 64
#define N_IS 64
#define T_IS 32

// ---------------- scratch (device globals; no allocation allowed) ----------------
__device__ float g_xproj_sc[(size_t)N_SC * T_SC * G4];   // [t][n][4H], bias folded
__device__ float g_xproj_cm[(size_t)N_CM * T_CM * G4];
__device__ float g_xproj_is[(size_t)N_IS * T_IS * G4];

__device__ float g_h_sc[2][N_SC * HDIM];
__device__ float g_c_sc[N_SC * HDIM];
__device__ float g_h_cm[2][N_CM * HDIM];
__device__ float g_c_cm[N_CM * HDIM];
__device__ float g_h_is[2][N_IS * HDIM];
__device__ float g_c_is[N_IS * HDIM];

__device__ float g_hm[N_SC];    // [B*NC] per-commit merged h scalar
__device__ float g_cmm[N_SC];

// ---------------- zero initial states ----------------
__global__ void zero_state() {
    int i = blockIdx.x * blockDim.x + threadIdx.x;
    if (i < N_SC * HDIM) {
        g_h_sc[0][i] = 0.f; g_c_sc[i] = 0.f;
        g_h_cm[0][i] = 0.f; g_c_cm[i] = 0.f;
    }
    if (i < N_IS * HDIM) {
        g_h_is[0][i] = 0.f; g_c_is[i] = 0.f;
    }
}

// ---------------- input projection: out[m][j] = emb[ids[n][t]] . Wih[j] + b[j]
// m = t*N + n  (t-major so each step reads a contiguous [N,4H] slab)
// Tiled GEMM: BM=64, BN=64, BK=32, 256 threads, 4x4 micro-tile (strided map).
__global__ void xproj_kernel(const int* __restrict__ ids,
                             const float* __restrict__ emb,
                             const float* __restrict__ Wih,   // [4H, E]
                             const float* __restrict__ bias,  // [4H]
                             int N, int T, int sel)
{
    float* out = (sel == 0) ? g_xproj_sc : (sel == 1) ? g_xproj_cm : g_xproj_is;

    __shared__ float As[64][33];
    __shared__ float Bs[32][65];
    __shared__ int   tok[64];

    const int m0 = blockIdx.x * 64;
    const int j0 = blockIdx.y * 64;
    const int tid = threadIdx.x;
    const int ty = tid >> 4, tx = tid & 15;

    if (tid < 64) {
        int m = m0 + tid;
        int t = m / N, n = m - t * N;
        tok[tid] = ids[n * T + t];
    }
    __syncthreads();

    float acc[4][4];
#pragma unroll
    for (int i = 0; i < 4; i++)
#pragma unroll
        for (int j = 0; j < 4; j++) acc[i][j] = 0.f;

    for (int k0 = 0; k0 < EDIM; k0 += 32) {
#pragma unroll
        for (int i = 0; i < 8; i++) {
            int lin = tid + i * 256;          // 2048 elems
            int r = lin >> 5, k = lin & 31;
            As[r][k] = emb[(size_t)tok[r] * EDIM + k0 + k];
        }
#pragma unroll
        for (int i = 0; i < 8; i++) {
            int lin = tid + i * 256;          // 2048 elems
            int j = lin >> 5, k = lin & 31;
            Bs[k][j] = Wih[(size_t)(j0 + j) * EDIM + k0 + k];
        }
        __syncthreads();
#pragma unroll
        for (int k = 0; k < 32; k++) {
            float a[4], b[4];
#pragma unroll
            for (int i = 0; i < 4; i++) a[i] = As[ty + 16 * i][k];
#pragma unroll
            for (int j = 0; j < 4; j++) b[j] = Bs[k][tx + 16 * j];
#pragma unroll
            for (int i = 0; i < 4; i++)
#pragma unroll
                for (int j = 0; j < 4; j++) acc[i][j] += a[i] * b[j];
        }
        __syncthreads();
    }

#pragma unroll
    for (int i = 0; i < 4; i++) {
        int m = m0 + ty + 16 * i;
#pragma unroll
        for (int j = 0; j < 4; j++) {
            int jj = j0 + tx + 16 * j;
            out[(size_t)m * G4 + jj] = acc[i][j] + bias[jj];
        }
    }
}

// ---------------- fused LSTM step for all three LSTMs at time t ----------------
// Block tile: 64 rows x 32 gate-cols x 4 gates of z = h@Whh.T, then pointwise.
// Grid: [0,160) sc ; [160,320) cm (if t<64) ; [320,336) is (if t<32)
__global__ void lstm_step_all(int t,
                              const float* __restrict__ Whh_sc,
                              const float* __restrict__ Whh_cm,
                              const float* __restrict__ Whh_is)
{
    __shared__ float As[64][33];
    __shared__ float Bs[4][32][33];

    int bid = blockIdx.x;
    const float* Whh; const float* xp; const float* h_in;
    float* h_out; float* c; int N;

    if (bid < 160) {
        Whh = Whh_sc; N = N_SC;
        xp = g_xproj_sc + (size_t)t * N_SC * G4;
        h_in = g_h_sc[t & 1]; h_out = g_h_sc[(t + 1) & 1]; c = g_c_sc;
    } else if (bid < 320) {
        bid -= 160;
        Whh = Whh_cm; N = N_CM;
        xp = g_xproj_cm + (size_t)t * N_CM * G4;
        h_in = g_h_cm[t & 1]; h_out = g_h_cm[(t + 1) & 1]; c = g_c_cm;
    } else {
        bid -= 320;
        Whh = Whh_is; N = N_IS;
        xp = g_xproj_is + (size_t)t * N_IS * G4;
        h_in = g_h_is[t & 1]; h_out = g_h_is[(t + 1) & 1]; c = g_c_is;
    }
    (void)N;

    const int rt = bid >> 4;          // row tile (64 rows)
    const int ct = bid & 15;          // col tile (32 of 512 gate cols)
    const int m0 = rt * 64;
    const int c0 = ct * 32;
    const int tid = threadIdx.x;
    const int ty = tid >> 4, tx = tid & 15;

    float acc[4][4][2];
#pragma unroll
    for (int g = 0; g < 4; g++)
#pragma unroll
        for (int i = 0; i < 4; i++) { acc[g][i][0] = 0.f; acc[g][i][1] = 0.f; }

    for (int k0 = 0; k0 < HDIM; k0 += 32) {
#pragma unroll
        for (int i = 0; i < 8; i++) {
            int lin = tid + i * 256;          // 64*32 = 2048
            int r = lin >> 5, k = lin & 31;
            As[r][k] = h_in[(size_t)(m0 + r) * HDIM + k0 + k];
        }
#pragma unroll
        for (int i = 0; i < 16; i++) {
            int lin = tid + i * 256;          // 4*32*32 = 4096
            int g = lin >> 10;
            int j = (lin >> 5) & 31;
            int k = lin & 31;
            Bs[g][k][j] = Whh[(size_t)(g * 512 + c0 + j) * HDIM + k0 + k];
        }
        __syncthreads();
#pragma unroll
        for (int k = 0; k < 32; k++) {
            float a[4];
#pragma unroll
            for (int i = 0; i < 4; i++) a[i] = As[ty + 16 * i][k];
#pragma unroll
            for (int g = 0; g < 4; g++) {
                float b0 = Bs[g][k][tx];
                float b1 = Bs[g][k][tx + 16];
#pragma unroll
                for (int i = 0; i < 4; i++) {
                    acc[g][i][0] += a[i] * b0;
                    acc[g][i][1] += a[i] * b1;
                }
            }
        }
        __syncthreads();
    }

    // pointwise epilogue
#pragma unroll
    for (int i = 0; i < 4; i++) {
        int m = m0 + ty + 16 * i;
#pragma unroll
        for (int j = 0; j < 2; j++) {
            int cg = c0 + tx + 16 * j;
            size_t xb = (size_t)m * G4 + cg;
            float zi = acc[0][i][j] + xp[xb];
            float zf = acc[1][i][j] + xp[xb + 512];
            float zg = acc[2][i][j] + xp[xb + 1024];
            float zo = acc[3][i][j] + xp[xb + 1536];
            float ig = 1.f / (1.f + expf(-zi));
            float fg = 1.f / (1.f + expf(-zf));
            float gg = tanhf(zg);
            float og = 1.f / (1.f + expf(-zo));
            size_t hi = (size_t)m * HDIM + cg;
            float cn = fg * c[hi] + ig * gg;
            c[hi] = cn;
            h_out[hi] = og * tanhf(cn);
        }
    }
}

// ---------------- merge: hm[n] = [h_sc|h_cm].Wmh + bmh ; cmm with c-states ------
__global__ void merge_kernel(const float* __restrict__ Wmh, const float* __restrict__ bmh,
                             const float* __restrict__ Wmc, const float* __restrict__ bmc)
{
    int wid = (blockIdx.x * blockDim.x + threadIdx.x) >> 5;
    int lane = threadIdx.x & 31;
    if (wid >= 2 * N_SC) return;
    int which = (wid >= N_SC);
    int n = which ? wid - N_SC : wid;
    const float* W = which ? Wmc : Wmh;
    const float* A = which ? g_c_sc : g_h_sc[0];
    const float* B = which ? g_c_cm : g_h_cm[0];
    float s = 0.f;
    for (int k = lane; k < HDIM; k += 32)
        s += A[(size_t)n * HDIM + k] * W[k] + B[(size_t)n * HDIM + k] * W[HDIM + k];
#pragma unroll
    for (int off = 16; off > 0; off >>= 1) s += __shfl_down_sync(0xffffffffu, s, off);
    if (lane == 0) {
        if (which) g_cmm[n] = s + bmc[0];
        else       g_hm[n]  = s + bmh[0];
    }
}

// ---------------- final: out_h[b][j] = [hm(10)|h_is(512)].Wfh[j] + bfh[j] -------
__global__ void final_kernel(const float* __restrict__ Wfh, const float* __restrict__ bfh,
                             const float* __restrict__ Wfc, const float* __restrict__ bfc,
                             float* __restrict__ out)
{
    int gw = (blockIdx.x * blockDim.x + threadIdx.x) >> 5;
    int lane = threadIdx.x & 31;
    if (gw >= 2 * 64 * HDIM) return;
    int which = (gw >= 64 * HDIM);
    int rem = which ? gw - 64 * HDIM : gw;
    int b = rem >> 9, j = rem & 511;
    const float* W  = which ? Wfc : Wfh;
    const float* mv = which ? g_cmm : g_hm;
    const float* hv = which ? g_c_is : g_h_is[0];
    const int K = 10 + HDIM;   // 522
    float s = 0.f;
    for (int k = lane; k < K; k += 32) {
        float x = (k < 10) ? mv[b * 10 + k] : hv[(size_t)b * HDIM + (k - 10)];
        s += W[(size_t)j * K + k] * x;
    }
#pragma unroll
    for (int off = 16; off > 0; off >>= 1) s += __shfl_down_sync(0xffffffffu, s, off);
    if (lane == 0) {
        float bias = which ? bfc[j] : bfh[j];
        out[(size_t)which * 64 * HDIM + (size_t)b * HDIM + j] = s + bias;
    }
}

// ---------------- launch ----------------
extern "C" void kernel_launch(void* const* d_in, const int* in_sizes, int n_in,
                              void* d_out, int out_size)
{
    (void)in_sizes; (void)n_in; (void)out_size;
    const int*   comments = (const int*)  d_in[0];
    const int*   cmids    = (const int*)  d_in[1];
    const int*   issue    = (const int*)  d_in[2];
    const float* emb_sc   = (const float*)d_in[3];
    const float* emb_cm   = (const float*)d_in[4];
    const float* emb_is   = (const float*)d_in[5];
    const float* Wih_sc   = (const float*)d_in[6];
    const float* Whh_sc   = (const float*)d_in[7];
    const float* b_sc     = (const float*)d_in[8];
    const float* Wih_cm   = (const float*)d_in[9];
    const float* Whh_cm   = (const float*)d_in[10];
    const float* b_cm     = (const float*)d_in[11];
    const float* Wih_is   = (const float*)d_in[12];
    const float* Whh_is   = (const float*)d_in[13];
    const float* b_is     = (const float*)d_in[14];
    const float* Wmh      = (const float*)d_in[15];
    const float* bmh      = (const float*)d_in[16];
    const float* Wmc      = (const float*)d_in[17];
    const float* bmc      = (const float*)d_in[18];
    const float* Wfh      = (const float*)d_in[19];
    const float* bfh      = (const float*)d_in[20];
    const float* Wfc      = (const float*)d_in[21];
    const float* bfc      = (const float*)d_in[22];

    zero_state<<<(N_SC * HDIM + 255) / 256, 256>>>();

    // input projections (parallel GEMMs, bias folded)
    xproj_kernel<<<dim3((N_SC * T_SC) / 64, 32), 256>>>(comments, emb_sc, Wih_sc, b_sc, N_SC, T_SC, 0);
    xproj_kernel<<<dim3((N_CM * T_CM) / 64, 32), 256>>>(cmids,    emb_cm, Wih_cm, b_cm, N_CM, T_CM, 1);
    xproj_kernel<<<dim3((N_IS * T_IS) / 64, 32), 256>>>(issue,    emb_is, Wih_is, b_is, N_IS, T_IS, 2);

    // recurrent steps: sc (128), cm (64) and is (32) ride in the same launches
    for (int t = 0; t < T_SC; t++) {
        int blocks = 160 + ((t < T_CM) ? 160 : 0) + ((t < T_IS) ? 16 : 0);
        lstm_step_all<<<blocks, 256>>>(t, Whh_sc, Whh_cm, Whh_is);
    }

    merge_kernel<<<(2 * N_SC * 32 + 255) / 256, 256>>>(Wmh, bmh, Wmc, bmc);
    final_kernel<<<(2 * 64 * HDIM * 32 + 255) / 256, 256>>>(Wfh, bfh, Wfc, bfc, (float*)d_out);
}

// round 5
// speedup vs baseline: 2.0718x; 2.0718x over previous
#include <cuda_runtime.h>
#include <cuda_bf16.h>
#include <cstdint>
#include <math.h>

typedef uint32_t u32;

#define HDIM 512
#define G4   2048
#define EDIM 256
#define N_SC 640
#define T_SC 128
#define N_CM 640
#define T_CM 64
#define N_ISP 128
#define N_IS_REAL 64
#define T_IS 32

#define KS_HH 32              // 512/16
#define KS_IH 16              // 256/16
#define NB_HH (256*KS_HH*32)  // uint2 elements
#define NB_IH (256*KS_IH*32)
#define ASTR  40              // smem A tile stride in bf16 (conflict-free)

// ---------------- device globals ----------------
__device__ uint2 g_WhhH[3][NB_HH], g_WhhL[3][NB_HH];
__device__ uint2 g_WihH[3][NB_IH], g_WihL[3][NB_IH];

__device__ __nv_bfloat16 g_ehi_sc[(size_t)N_SC*T_SC*EDIM], g_elo_sc[(size_t)N_SC*T_SC*EDIM];
__device__ __nv_bfloat16 g_ehi_cm[(size_t)N_CM*T_CM*EDIM], g_elo_cm[(size_t)N_CM*T_CM*EDIM];
__device__ __nv_bfloat16 g_ehi_is[(size_t)N_ISP*T_IS*EDIM], g_elo_is[(size_t)N_ISP*T_IS*EDIM];

__device__ float g_xp_sc[(size_t)N_SC*T_SC*G4];
__device__ float g_xp_cm[(size_t)N_CM*T_CM*G4];
__device__ float g_xp_is[(size_t)N_ISP*T_IS*G4];

__device__ __nv_bfloat16 g_hhi_sc[2][N_SC*HDIM], g_hlo_sc[2][N_SC*HDIM];
__device__ __nv_bfloat16 g_hhi_cm[2][N_CM*HDIM], g_hlo_cm[2][N_CM*HDIM];
__device__ __nv_bfloat16 g_hhi_is[2][N_ISP*HDIM], g_hlo_is[2][N_ISP*HDIM];
__device__ float g_c_sc[N_SC*HDIM], g_c_cm[N_CM*HDIM], g_c_is[N_ISP*HDIM];
__device__ float g_hm[N_SC], g_cmm[N_SC];

// ---------------- helpers ----------------
__device__ __forceinline__ void mma_bf16(float* c, const u32* a, const u32* b) {
    asm volatile("mma.sync.aligned.m16n8k16.row.col.f32.bf16.bf16.f32 "
        "{%0,%1,%2,%3}, {%4,%5,%6,%7}, {%8,%9}, {%0,%1,%2,%3};"
        : "+f"(c[0]), "+f"(c[1]), "+f"(c[2]), "+f"(c[3])
        : "r"(a[0]), "r"(a[1]), "r"(a[2]), "r"(a[3]), "r"(b[0]), "r"(b[1]));
}
__device__ __forceinline__ u32 pk2(float a, float b) {
    __nv_bfloat162 v;
    v.x = __float2bfloat16(a); v.y = __float2bfloat16(b);
    return *(u32*)&v;
}
__device__ __forceinline__ float rsd(float a) {
    return a - __bfloat162float(__float2bfloat16(a));
}
__device__ __forceinline__ float sigf(float x) { return 1.f / (1.f + __expf(-x)); }
__device__ __forceinline__ float tanh_f(float x) { return 2.f / (1.f + __expf(-2.f * x)) - 1.f; }

// ---------------- prep kernels ----------------
__global__ void zero_state_k() {
    int i = blockIdx.x * blockDim.x + threadIdx.x;
    __nv_bfloat16 z = __float2bfloat16(0.f);
    if (i < N_SC * HDIM) {
        g_hhi_sc[0][i] = z; g_hlo_sc[0][i] = z; g_c_sc[i] = 0.f;
        g_hhi_cm[0][i] = z; g_hlo_cm[0][i] = z; g_c_cm[i] = 0.f;
    }
    if (i < N_ISP * HDIM) { g_hhi_is[0][i] = z; g_hlo_is[0][i] = z; g_c_is[i] = 0.f; }
}

// pack W rows into per-lane mma B-fragment order (hi and lo)
__global__ void prep_w(const float* __restrict__ Whh, const float* __restrict__ Wih, int sel) {
    int idx = blockIdx.x * blockDim.x + threadIdx.x;
    if (idx < NB_HH) {
        int lane = idx & 31, rest = idx >> 5;
        int ks = rest % KS_HH, j8 = rest / KS_HH;
        int g = lane >> 2, tq = lane & 3;
        const float* Wr = Whh + (size_t)(j8 * 8 + g) * HDIM + ks * 16 + tq * 2;
        float w0 = Wr[0], w1 = Wr[1], w8 = Wr[8], w9 = Wr[9];
        g_WhhH[sel][idx] = make_uint2(pk2(w0, w1), pk2(w8, w9));
        g_WhhL[sel][idx] = make_uint2(pk2(rsd(w0), rsd(w1)), pk2(rsd(w8), rsd(w9)));
    } else {
        int id2 = idx - NB_HH;
        if (id2 < NB_IH) {
            int lane = id2 & 31, rest = id2 >> 5;
            int ks = rest % KS_IH, j8 = rest / KS_IH;
            int g = lane >> 2, tq = lane & 3;
            const float* Wr = Wih + (size_t)(j8 * 8 + g) * EDIM + ks * 16 + tq * 2;
            float w0 = Wr[0], w1 = Wr[1], w8 = Wr[8], w9 = Wr[9];
            g_WihH[sel][id2] = make_uint2(pk2(w0, w1), pk2(w8, w9));
            g_WihL[sel][id2] = make_uint2(pk2(rsd(w0), rsd(w1)), pk2(rsd(w8), rsd(w9)));
        }
    }
}

// gather + hi/lo split embeddings, t-major rows
__global__ void prep_embed(const int* __restrict__ ids, const float* __restrict__ emb,
                           int sel, int Nreal, int Npad, int T) {
    __nv_bfloat16* hi = sel == 0 ? g_ehi_sc : sel == 1 ? g_ehi_cm : g_ehi_is;
    __nv_bfloat16* lo = sel == 0 ? g_elo_sc : sel == 1 ? g_elo_cm : g_elo_is;
    size_t idx = (size_t)blockIdx.x * blockDim.x + threadIdx.x;
    size_t total = (size_t)Npad * T * 64;
    if (idx >= total) return;
    int q = (int)(idx & 63);
    size_t r = idx >> 6;
    int n = (int)(r % Npad);
    int tt = (int)(r / Npad);
    float4 v = make_float4(0.f, 0.f, 0.f, 0.f);
    if (n < Nreal) {
        int tok = ids[(size_t)n * T + tt];
        v = ((const float4*)(emb + (size_t)tok * EDIM))[q];
    }
    __nv_bfloat16 h0 = __float2bfloat16(v.x), h1 = __float2bfloat16(v.y);
    __nv_bfloat16 h2 = __float2bfloat16(v.z), h3 = __float2bfloat16(v.w);
    size_t o = r * EDIM + (size_t)q * 4;
    __nv_bfloat162* ph = (__nv_bfloat162*)(hi + o);
    __nv_bfloat162* pl = (__nv_bfloat162*)(lo + o);
    ph[0] = __nv_bfloat162(h0, h1); ph[1] = __nv_bfloat162(h2, h3);
    pl[0] = __nv_bfloat162(__float2bfloat16(v.x - __bfloat162float(h0)),
                           __float2bfloat16(v.y - __bfloat162float(h1)));
    pl[1] = __nv_bfloat162(__float2bfloat16(v.z - __bfloat162float(h2)),
                           __float2bfloat16(v.w - __bfloat162float(h3)));
}

// ---------------- xproj GEMM (HMMA, 3-product): xp[m][j] = e[m].Wih[j] + b[j] ----
__global__ void __launch_bounds__(256)
xproj_mma(int sel, const float* __restrict__ bias) {
    const __nv_bfloat16* ehi = sel == 0 ? g_ehi_sc : sel == 1 ? g_ehi_cm : g_ehi_is;
    const __nv_bfloat16* elo = sel == 0 ? g_elo_sc : sel == 1 ? g_elo_cm : g_elo_is;
    const uint2* BH = g_WihH[sel];
    const uint2* BL = g_WihL[sel];
    float* xp = sel == 0 ? g_xp_sc : sel == 1 ? g_xp_cm : g_xp_is;

    __shared__ __nv_bfloat16 Ah[128 * ASTR], Al[128 * ASTR];

    const int tid = threadIdx.x, lane = tid & 31, warp = tid >> 5;
    const int wm = warp >> 1, wn = warp & 1;
    const int g = lane >> 2, tq = lane & 3;
    const int m0 = blockIdx.x * 128;
    const int n0 = blockIdx.y * 128;

    float c[2][8][4];
#pragma unroll
    for (int i = 0; i < 2; i++)
#pragma unroll
        for (int j = 0; j < 8; j++)
#pragma unroll
            for (int q = 0; q < 4; q++) c[i][j][q] = 0.f;

    for (int ch = 0; ch < EDIM / 32; ch++) {
#pragma unroll
        for (int i = 0; i < 2; i++) {
            int lin = tid + i * 256;
            int r = lin >> 2, q = lin & 3;
            size_t off = (size_t)(m0 + r) * EDIM + ch * 32 + q * 8;
            *(uint4*)(Ah + r * ASTR + q * 8) = *(const uint4*)(ehi + off);
            *(uint4*)(Al + r * ASTR + q * 8) = *(const uint4*)(elo + off);
        }
        __syncthreads();
#pragma unroll
        for (int kk = 0; kk < 2; kk++) {
            u32 AH[2][4], AL[2][4];
#pragma unroll
            for (int i = 0; i < 2; i++) {
                const __nv_bfloat16* p = Ah + (wm * 32 + i * 16 + g) * ASTR + kk * 16 + tq * 2;
                AH[i][0] = *(const u32*)p;
                AH[i][1] = *(const u32*)(p + 8 * ASTR);
                AH[i][2] = *(const u32*)(p + 8);
                AH[i][3] = *(const u32*)(p + 8 * ASTR + 8);
                const __nv_bfloat16* q2 = Al + (wm * 32 + i * 16 + g) * ASTR + kk * 16 + tq * 2;
                AL[i][0] = *(const u32*)q2;
                AL[i][1] = *(const u32*)(q2 + 8 * ASTR);
                AL[i][2] = *(const u32*)(q2 + 8);
                AL[i][3] = *(const u32*)(q2 + 8 * ASTR + 8);
            }
#pragma unroll
            for (int j = 0; j < 8; j++) {
                int j8 = (n0 >> 3) + wn * 8 + j;
                int bi = (j8 * KS_IH + ch * 2 + kk) * 32 + lane;
                uint2 bh = BH[bi], bl = BL[bi];
                u32 bhr[2] = {bh.x, bh.y}, blr[2] = {bl.x, bl.y};
                mma_bf16(c[0][j], AH[0], bhr); mma_bf16(c[1][j], AH[1], bhr);
                mma_bf16(c[0][j], AL[0], bhr); mma_bf16(c[1][j], AL[1], bhr);
                mma_bf16(c[0][j], AH[0], blr); mma_bf16(c[1][j], AH[1], blr);
            }
        }
        __syncthreads();
    }

#pragma unroll
    for (int i = 0; i < 2; i++)
#pragma unroll
        for (int j = 0; j < 8; j++) {
            int row = m0 + wm * 32 + i * 16 + g;
            int col = n0 + wn * 64 + j * 8 + tq * 2;
            float2 v0 = make_float2(c[i][j][0] + bias[col], c[i][j][1] + bias[col + 1]);
            *(float2*)&xp[(size_t)row * G4 + col] = v0;
            float2 v1 = make_float2(c[i][j][2] + bias[col], c[i][j][3] + bias[col + 1]);
            *(float2*)&xp[(size_t)(row + 8) * G4 + col] = v1;
        }
}

// ---------------- fused recurrent step (HMMA + gates) ----------------
// grid: [0,80) sc ; [80,160) cm ; [160,176) is.  tile: 128 rows x (4 gates x 32 hc)
__global__ void __launch_bounds__(256)
step_mma(int t) {
    extern __shared__ char smem[];
    __nv_bfloat16* Ah = (__nv_bfloat16*)smem;
    __nv_bfloat16* Al = Ah + 128 * ASTR;
    float* zs = (float*)smem;   // reused after mainloop: [128][132]

    int bid = blockIdx.x;
    const __nv_bfloat16 *hhin, *hlin;
    __nv_bfloat16 *hhout, *hlout;
    const uint2 *BH, *BL;
    float *cst; const float* xp;
    int m0, hc0;

    if (bid < 80) {
        BH = g_WhhH[0]; BL = g_WhhL[0];
        hhin = g_hhi_sc[t & 1]; hlin = g_hlo_sc[t & 1];
        hhout = g_hhi_sc[(t + 1) & 1]; hlout = g_hlo_sc[(t + 1) & 1];
        cst = g_c_sc; xp = g_xp_sc + (size_t)t * N_SC * G4;
        m0 = (bid >> 4) * 128; hc0 = (bid & 15) * 32;
    } else if (bid < 160) {
        bid -= 80;
        BH = g_WhhH[1]; BL = g_WhhL[1];
        hhin = g_hhi_cm[t & 1]; hlin = g_hlo_cm[t & 1];
        hhout = g_hhi_cm[(t + 1) & 1]; hlout = g_hlo_cm[(t + 1) & 1];
        cst = g_c_cm; xp = g_xp_cm + (size_t)t * N_CM * G4;
        m0 = (bid >> 4) * 128; hc0 = (bid & 15) * 32;
    } else {
        bid -= 160;
        BH = g_WhhH[2]; BL = g_WhhL[2];
        hhin = g_hhi_is[t & 1]; hlin = g_hlo_is[t & 1];
        hhout = g_hhi_is[(t + 1) & 1]; hlout = g_hlo_is[(t + 1) & 1];
        cst = g_c_is; xp = g_xp_is + (size_t)t * N_ISP * G4;
        m0 = 0; hc0 = bid * 32;
    }

    const int tid = threadIdx.x, lane = tid & 31, warp = tid >> 5;
    const int wm = warp >> 1, wn = warp & 1;
    const int g = lane >> 2, tq = lane & 3;

    float c[2][8][4];
#pragma unroll
    for (int i = 0; i < 2; i++)
#pragma unroll
        for (int j = 0; j < 8; j++)
#pragma unroll
            for (int q = 0; q < 4; q++) c[i][j][q] = 0.f;

    for (int ch = 0; ch < HDIM / 32; ch++) {
#pragma unroll
        for (int i = 0; i < 2; i++) {
            int lin = tid + i * 256;
            int r = lin >> 2, q = lin & 3;
            size_t off = (size_t)(m0 + r) * HDIM + ch * 32 + q * 8;
            *(uint4*)(Ah + r * ASTR + q * 8) = *(const uint4*)(hhin + off);
            *(uint4*)(Al + r * ASTR + q * 8) = *(const uint4*)(hlin + off);
        }
        __syncthreads();
#pragma unroll
        for (int kk = 0; kk < 2; kk++) {
            u32 AH[2][4], AL[2][4];
#pragma unroll
            for (int i = 0; i < 2; i++) {
                const __nv_bfloat16* p = Ah + (wm * 32 + i * 16 + g) * ASTR + kk * 16 + tq * 2;
                AH[i][0] = *(const u32*)p;
                AH[i][1] = *(const u32*)(p + 8 * ASTR);
                AH[i][2] = *(const u32*)(p + 8);
                AH[i][3] = *(const u32*)(p + 8 * ASTR + 8);
                const __nv_bfloat16* q2 = Al + (wm * 32 + i * 16 + g) * ASTR + kk * 16 + tq * 2;
                AL[i][0] = *(const u32*)q2;
                AL[i][1] = *(const u32*)(q2 + 8 * ASTR);
                AL[i][2] = *(const u32*)(q2 + 8);
                AL[i][3] = *(const u32*)(q2 + 8 * ASTR + 8);
            }
#pragma unroll
            for (int j = 0; j < 8; j++) {
                int gi = 2 * wn + (j >> 2);
                int j8 = gi * 64 + (hc0 >> 3) + (j & 3);
                int bi = (j8 * KS_HH + ch * 2 + kk) * 32 + lane;
                uint2 bh = BH[bi], bl = BL[bi];
                u32 bhr[2] = {bh.x, bh.y}, blr[2] = {bl.x, bl.y};
                mma_bf16(c[0][j], AH[0], bhr); mma_bf16(c[1][j], AH[1], bhr);
                mma_bf16(c[0][j], AL[0], bhr); mma_bf16(c[1][j], AL[1], bhr);
                mma_bf16(c[0][j], AH[0], blr); mma_bf16(c[1][j], AH[1], blr);
            }
        }
        __syncthreads();
    }

    // stage z into smem: col = gate*32 + hc_local
#pragma unroll
    for (int i = 0; i < 2; i++)
#pragma unroll
        for (int j = 0; j < 8; j++) {
            int row = wm * 32 + i * 16 + g;
            int colz = (2 * wn + (j >> 2)) * 32 + (j & 3) * 8 + tq * 2;
            *(float2*)&zs[row * 132 + colz] = make_float2(c[i][j][0], c[i][j][1]);
            *(float2*)&zs[(row + 8) * 132 + colz] = make_float2(c[i][j][2], c[i][j][3]);
        }
    __syncthreads();

    // pointwise: each thread 4 contiguous hidden cols
#pragma unroll
    for (int it = 0; it < 4; it++) {
        int r = (tid >> 3) + it * 32;
        int hc = (tid & 7) * 4;
        int m = m0 + r, hcg = hc0 + hc;
        const float* zr = zs + r * 132 + hc;
        float4 zi = *(const float4*)(zr);
        float4 zf = *(const float4*)(zr + 32);
        float4 zg = *(const float4*)(zr + 64);
        float4 zo = *(const float4*)(zr + 96);
        const float* xr = xp + (size_t)m * G4 + hcg;
        float4 xi = *(const float4*)(xr);
        float4 xf = *(const float4*)(xr + 512);
        float4 xg = *(const float4*)(xr + 1024);
        float4 xo = *(const float4*)(xr + 1536);
        float vi[4] = {zi.x + xi.x, zi.y + xi.y, zi.z + xi.z, zi.w + xi.w};
        float vf[4] = {zf.x + xf.x, zf.y + xf.y, zf.z + xf.z, zf.w + xf.w};
        float vg[4] = {zg.x + xg.x, zg.y + xg.y, zg.z + xg.z, zg.w + xg.w};
        float vo[4] = {zo.x + xo.x, zo.y + xo.y, zo.z + xo.z, zo.w + xo.w};
        float* cp = cst + (size_t)m * HDIM + hcg;
        float4 cv = *(const float4*)cp;
        float cc[4] = {cv.x, cv.y, cv.z, cv.w};
        float hv[4];
#pragma unroll
        for (int q = 0; q < 4; q++) {
            float ig = sigf(vi[q]), fg = sigf(vf[q]);
            float gg = tanh_f(vg[q]), og = sigf(vo[q]);
            float cn = fg * cc[q] + ig * gg;
            cc[q] = cn;
            hv[q] = og * tanh_f(cn);
        }
        *(float4*)cp = make_float4(cc[0], cc[1], cc[2], cc[3]);
        __nv_bfloat16 h0 = __float2bfloat16(hv[0]), h1 = __float2bfloat16(hv[1]);
        __nv_bfloat16 h2 = __float2bfloat16(hv[2]), h3 = __float2bfloat16(hv[3]);
        __nv_bfloat162* ph = (__nv_bfloat162*)(hhout + (size_t)m * HDIM + hcg);
        ph[0] = __nv_bfloat162(h0, h1); ph[1] = __nv_bfloat162(h2, h3);
        __nv_bfloat162* pl = (__nv_bfloat162*)(hlout + (size_t)m * HDIM + hcg);
        pl[0] = __nv_bfloat162(__float2bfloat16(hv[0] - __bfloat162float(h0)),
                               __float2bfloat16(hv[1] - __bfloat162float(h1)));
        pl[1] = __nv_bfloat162(__float2bfloat16(hv[2] - __bfloat162float(h2)),
                               __float2bfloat16(hv[3] - __bfloat162float(h3)));
    }
}

// ---------------- merge & final ----------------
__global__ void merge_kernel(const float* __restrict__ Wmh, const float* __restrict__ bmh,
                             const float* __restrict__ Wmc, const float* __restrict__ bmc)
{
    int wg = (blockIdx.x * blockDim.x + threadIdx.x) >> 5;
    int lane = threadIdx.x & 31;
    if (wg >= 2 * N_SC) return;
    int which = (wg >= N_SC);
    int n = which ? wg - N_SC : wg;
    const float* W = which ? Wmc : Wmh;
    float s = 0.f;
    for (int k = lane; k < HDIM; k += 32) {
        size_t i = (size_t)n * HDIM + k;
        float a, b;
        if (which) { a = g_c_sc[i]; b = g_c_cm[i]; }
        else {
            a = __bfloat162float(g_hhi_sc[0][i]) + __bfloat162float(g_hlo_sc[0][i]);
            b = __bfloat162float(g_hhi_cm[0][i]) + __bfloat162float(g_hlo_cm[0][i]);
        }
        s += a * W[k] + b * W[HDIM + k];
    }
#pragma unroll
    for (int off = 16; off > 0; off >>= 1) s += __shfl_down_sync(0xffffffffu, s, off);
    if (lane == 0) {
        if (which) g_cmm[n] = s + bmc[0];
        else       g_hm[n]  = s + bmh[0];
    }
}

__global__ void final_kernel(const float* __restrict__ Wfh, const float* __restrict__ bfh,
                             const float* __restrict__ Wfc, const float* __restrict__ bfc,
                             float* __restrict__ out)
{
    int gw = (blockIdx.x * blockDim.x + threadIdx.x) >> 5;
    int lane = threadIdx.x & 31;
    if (gw >= 2 * 64 * HDIM) return;
    int which = (gw >= 64 * HDIM);
    int rem = which ? gw - 64 * HDIM : gw;
    int b = rem >> 9, j = rem & 511;
    const float* W  = which ? Wfc : Wfh;
    const float* mv = which ? g_cmm : g_hm;
    const int K = 10 + HDIM;
    float s = 0.f;
    for (int k = lane; k < K; k += 32) {
        float x;
        if (k < 10) x = mv[b * 10 + k];
        else {
            size_t i = (size_t)b * HDIM + (k - 10);
            x = which ? g_c_is[i]
                      : __bfloat162float(g_hhi_is[0][i]) + __bfloat162float(g_hlo_is[0][i]);
        }
        s += W[(size_t)j * K + k] * x;
    }
#pragma unroll
    for (int off = 16; off > 0; off >>= 1) s += __shfl_down_sync(0xffffffffu, s, off);
    if (lane == 0) {
        float bias = which ? bfc[j] : bfh[j];
        out[(size_t)which * 64 * HDIM + (size_t)b * HDIM + j] = s + bias;
    }
}

// ---------------- launch ----------------
extern "C" void kernel_launch(void* const* d_in, const int* in_sizes, int n_in,
                              void* d_out, int out_size)
{
    (void)in_sizes; (void)n_in; (void)out_size;
    const int*   comments = (const int*)  d_in[0];
    const int*   cmids    = (const int*)  d_in[1];
    const int*   issue    = (const int*)  d_in[2];
    const float* emb_sc   = (const float*)d_in[3];
    const float* emb_cm   = (const float*)d_in[4];
    const float* emb_is   = (const float*)d_in[5];
    const float* Wih_sc   = (const float*)d_in[6];
    const float* Whh_sc   = (const float*)d_in[7];
    const float* b_sc     = (const float*)d_in[8];
    const float* Wih_cm   = (const float*)d_in[9];
    const float* Whh_cm   = (const float*)d_in[10];
    const float* b_cm     = (const float*)d_in[11];
    const float* Wih_is   = (const float*)d_in[12];
    const float* Whh_is   = (const float*)d_in[13];
    const float* b_is     = (const float*)d_in[14];
    const float* Wmh      = (const float*)d_in[15];
    const float* bmh      = (const float*)d_in[16];
    const float* Wmc      = (const float*)d_in[17];
    const float* bmc      = (const float*)d_in[18];
    const float* Wfh      = (const float*)d_in[19];
    const float* bfh      = (const float*)d_in[20];
    const float* Wfc      = (const float*)d_in[21];
    const float* bfc      = (const float*)d_in[22];

    static int smem_set = 0;
    if (!smem_set) {
        cudaFuncSetAttribute(step_mma, cudaFuncAttributeMaxDynamicSharedMemorySize, 128 * 132 * 4);
        smem_set = 1;
    }

    zero_state_k<<<(N_SC * HDIM + 255) / 256, 256>>>();
    prep_w<<<(NB_HH + NB_IH + 255) / 256, 256>>>(Whh_sc, Wih_sc, 0);
    prep_w<<<(NB_HH + NB_IH + 255) / 256, 256>>>(Whh_cm, Wih_cm, 1);
    prep_w<<<(NB_HH + NB_IH + 255) / 256, 256>>>(Whh_is, Wih_is, 2);
    prep_embed<<<(int)(((size_t)N_SC * T_SC * 64 + 255) / 256), 256>>>(comments, emb_sc, 0, N_SC, N_SC, T_SC);
    prep_embed<<<(int)(((size_t)N_CM * T_CM * 64 + 255) / 256), 256>>>(cmids, emb_cm, 1, N_CM, N_CM, T_CM);
    prep_embed<<<(int)(((size_t)N_ISP * T_IS * 64 + 255) / 256), 256>>>(issue, emb_is, 2, N_IS_REAL, N_ISP, T_IS);

    xproj_mma<<<dim3(N_SC * T_SC / 128, 16), 256>>>(0, b_sc);
    xproj_mma<<<dim3(N_CM * T_CM / 128, 16), 256>>>(1, b_cm);
    xproj_mma<<<dim3(N_ISP * T_IS / 128, 16), 256>>>(2, b_is);

    for (int t = 0; t < T_SC; t++) {
        int blocks = 80 + ((t < T_CM) ? 80 : 0) + ((t < T_IS) ? 16 : 0);
        step_mma<<<blocks, 256, 128 * 132 * 4>>>(t);
    }

    merge_kernel<<<(2 * N_SC * 32 + 255) / 256, 256>>>(Wmh, bmh, Wmc, bmc);
    final_kernel<<<(2 * 64 * HDIM * 32 + 255) / 256, 256>>>(Wfh, bfh, Wfc, bfc, (float*)d_out);
}

// round 6
// speedup vs baseline: 3.3391x; 1.6117x over previous
#include <cuda_runtime.h>
#include <cuda_bf16.h>
#include <cstdint>
#include <math.h>

typedef uint32_t u32;

#define HDIM 512
#define G4   2048
#define EDIM 256
#define N_SC 640
#define T_SC 128
#define N_CM 640
#define T_CM 64
#define N_ISP 128
#define N_IS_REAL 64
#define T_IS 32

#define KS_HH 32              // 512/16
#define KS_IH 16              // 256/16
#define NB_HH (256*KS_HH*32)  // uint2 elements
#define NB_IH (256*KS_IH*32)
#define ASTR  40              // smem A tile stride in bf16 (conflict-free)

#define STEP_SMEM (64*132*4)  // z staging 33792 B (A tiles overlap at offset 0)

// ---------------- device globals ----------------
__device__ uint2 g_WhhH[3][NB_HH], g_WhhL[3][NB_HH];
__device__ uint2 g_WihH[3][NB_IH], g_WihL[3][NB_IH];

__device__ __nv_bfloat16 g_ehi_sc[(size_t)N_SC*T_SC*EDIM], g_elo_sc[(size_t)N_SC*T_SC*EDIM];
__device__ __nv_bfloat16 g_ehi_cm[(size_t)N_CM*T_CM*EDIM], g_elo_cm[(size_t)N_CM*T_CM*EDIM];
__device__ __nv_bfloat16 g_ehi_is[(size_t)N_ISP*T_IS*EDIM], g_elo_is[(size_t)N_ISP*T_IS*EDIM];

__device__ float g_xp_sc[(size_t)N_SC*T_SC*G4];
__device__ float g_xp_cm[(size_t)N_CM*T_CM*G4];
__device__ float g_xp_is[(size_t)N_ISP*T_IS*G4];

__device__ __nv_bfloat16 g_hhi_sc[2][N_SC*HDIM], g_hlo_sc[2][N_SC*HDIM];
__device__ __nv_bfloat16 g_hhi_cm[2][N_CM*HDIM], g_hlo_cm[2][N_CM*HDIM];
__device__ __nv_bfloat16 g_hhi_is[2][N_ISP*HDIM], g_hlo_is[2][N_ISP*HDIM];
__device__ float g_c_sc[N_SC*HDIM], g_c_cm[N_CM*HDIM], g_c_is[N_ISP*HDIM];
__device__ float g_hm[N_SC], g_cmm[N_SC];

// ---------------- helpers ----------------
__device__ __forceinline__ void mma_bf16(float* c, const u32* a, const u32* b) {
    asm volatile("mma.sync.aligned.m16n8k16.row.col.f32.bf16.bf16.f32 "
        "{%0,%1,%2,%3}, {%4,%5,%6,%7}, {%8,%9}, {%0,%1,%2,%3};"
        : "+f"(c[0]), "+f"(c[1]), "+f"(c[2]), "+f"(c[3])
        : "r"(a[0]), "r"(a[1]), "r"(a[2]), "r"(a[3]), "r"(b[0]), "r"(b[1]));
}
__device__ __forceinline__ u32 pk2(float a, float b) {
    __nv_bfloat162 v;
    v.x = __float2bfloat16(a); v.y = __float2bfloat16(b);
    return *(u32*)&v;
}
__device__ __forceinline__ float rsd(float a) {
    return a - __bfloat162float(__float2bfloat16(a));
}
__device__ __forceinline__ float sigf(float x) { return 1.f / (1.f + __expf(-x)); }
__device__ __forceinline__ float tanh_f(float x) { return 2.f / (1.f + __expf(-2.f * x)) - 1.f; }

// ---------------- prep kernels ----------------
__global__ void zero_state_k() {
    int i = blockIdx.x * blockDim.x + threadIdx.x;
    __nv_bfloat16 z = __float2bfloat16(0.f);
    if (i < N_SC * HDIM) {
        g_hhi_sc[0][i] = z; g_hlo_sc[0][i] = z; g_c_sc[i] = 0.f;
        g_hhi_cm[0][i] = z; g_hlo_cm[0][i] = z; g_c_cm[i] = 0.f;
    }
    if (i < N_ISP * HDIM) { g_hhi_is[0][i] = z; g_hlo_is[0][i] = z; g_c_is[i] = 0.f; }
}

__global__ void prep_w(const float* __restrict__ Whh, const float* __restrict__ Wih, int sel) {
    int idx = blockIdx.x * blockDim.x + threadIdx.x;
    if (idx < NB_HH) {
        int lane = idx & 31, rest = idx >> 5;
        int ks = rest % KS_HH, j8 = rest / KS_HH;
        int g = lane >> 2, tq = lane & 3;
        const float* Wr = Whh + (size_t)(j8 * 8 + g) * HDIM + ks * 16 + tq * 2;
        float w0 = Wr[0], w1 = Wr[1], w8 = Wr[8], w9 = Wr[9];
        g_WhhH[sel][idx] = make_uint2(pk2(w0, w1), pk2(w8, w9));
        g_WhhL[sel][idx] = make_uint2(pk2(rsd(w0), rsd(w1)), pk2(rsd(w8), rsd(w9)));
    } else {
        int id2 = idx - NB_HH;
        if (id2 < NB_IH) {
            int lane = id2 & 31, rest = id2 >> 5;
            int ks = rest % KS_IH, j8 = rest / KS_IH;
            int g = lane >> 2, tq = lane & 3;
            const float* Wr = Wih + (size_t)(j8 * 8 + g) * EDIM + ks * 16 + tq * 2;
            float w0 = Wr[0], w1 = Wr[1], w8 = Wr[8], w9 = Wr[9];
            g_WihH[sel][id2] = make_uint2(pk2(w0, w1), pk2(w8, w9));
            g_WihL[sel][id2] = make_uint2(pk2(rsd(w0), rsd(w1)), pk2(rsd(w8), rsd(w9)));
        }
    }
}

__global__ void prep_embed(const int* __restrict__ ids, const float* __restrict__ emb,
                           int sel, int Nreal, int Npad, int T) {
    __nv_bfloat16* hi = sel == 0 ? g_ehi_sc : sel == 1 ? g_ehi_cm : g_ehi_is;
    __nv_bfloat16* lo = sel == 0 ? g_elo_sc : sel == 1 ? g_elo_cm : g_elo_is;
    size_t idx = (size_t)blockIdx.x * blockDim.x + threadIdx.x;
    size_t total = (size_t)Npad * T * 64;
    if (idx >= total) return;
    int q = (int)(idx & 63);
    size_t r = idx >> 6;
    int n = (int)(r % Npad);
    int tt = (int)(r / Npad);
    float4 v = make_float4(0.f, 0.f, 0.f, 0.f);
    if (n < Nreal) {
        int tok = ids[(size_t)n * T + tt];
        v = ((const float4*)(emb + (size_t)tok * EDIM))[q];
    }
    __nv_bfloat16 h0 = __float2bfloat16(v.x), h1 = __float2bfloat16(v.y);
    __nv_bfloat16 h2 = __float2bfloat16(v.z), h3 = __float2bfloat16(v.w);
    size_t o = r * EDIM + (size_t)q * 4;
    __nv_bfloat162* ph = (__nv_bfloat162*)(hi + o);
    __nv_bfloat162* pl = (__nv_bfloat162*)(lo + o);
    ph[0] = __nv_bfloat162(h0, h1); ph[1] = __nv_bfloat162(h2, h3);
    pl[0] = __nv_bfloat162(__float2bfloat16(v.x - __bfloat162float(h0)),
                           __float2bfloat16(v.y - __bfloat162float(h1)));
    pl[1] = __nv_bfloat162(__float2bfloat16(v.z - __bfloat162float(h2)),
                           __float2bfloat16(v.w - __bfloat162float(h3)));
}

// ---------------- xproj GEMM: pipelined HMMA, M=64 x N=128 tile ----------------
__global__ void __launch_bounds__(256, 2)
xproj_mma(int sel, const float* __restrict__ bias) {
    const __nv_bfloat16* ehi = sel == 0 ? g_ehi_sc : sel == 1 ? g_ehi_cm : g_ehi_is;
    const __nv_bfloat16* elo = sel == 0 ? g_elo_sc : sel == 1 ? g_elo_cm : g_elo_is;
    const uint2* __restrict__ BHp = g_WihH[sel];
    const uint2* __restrict__ BLp = g_WihL[sel];
    float* xp = sel == 0 ? g_xp_sc : sel == 1 ? g_xp_cm : g_xp_is;

    __shared__ __nv_bfloat16 Ah[64 * ASTR], Al[64 * ASTR];

    const int tid = threadIdx.x, lane = tid & 31, warp = tid >> 5;
    const int wm = warp & 1, wn = warp >> 1;      // wm: 2x32 rows, wn: 4x32 cols
    const int g = lane >> 2, tq = lane & 3;
    const int m0 = blockIdx.x * 64;
    const int n0 = blockIdx.y * 128;

    const int ar = tid >> 2, aq = tid & 3;        // A copy role: row, 16B-quarter
    const u32 asts = (u32)(ar * ASTR + aq * 8);

    float acc[2][4][4];
#pragma unroll
    for (int i = 0; i < 2; i++)
#pragma unroll
        for (int j = 0; j < 4; j++)
#pragma unroll
            for (int q = 0; q < 4; q++) acc[i][j][q] = 0.f;

    // prologue: A chunk 0
    {
        size_t off = (size_t)(m0 + ar) * EDIM + aq * 8;
        uint4 vh = *(const uint4*)(ehi + off);
        uint4 vl = *(const uint4*)(elo + off);
        *(uint4*)(Ah + asts) = vh;
        *(uint4*)(Al + asts) = vl;
    }
    __syncthreads();

#pragma unroll 1
    for (int ch = 0; ch < EDIM / 32; ch++) {
        uint4 nh, nl;
        bool has_next = (ch + 1) < EDIM / 32;
        if (has_next) {
            size_t off = (size_t)(m0 + ar) * EDIM + (ch + 1) * 32 + aq * 8;
            nh = *(const uint4*)(ehi + off);
            nl = *(const uint4*)(elo + off);
        }
        // B fragments for whole chunk
        uint2 BH[2][4], BL[2][4];
#pragma unroll
        for (int kk = 0; kk < 2; kk++)
#pragma unroll
            for (int j = 0; j < 4; j++) {
                int j8 = (n0 >> 3) + wn * 4 + j;
                int bi = (j8 * KS_IH + ch * 2 + kk) * 32 + lane;
                BH[kk][j] = BHp[bi];
                BL[kk][j] = BLp[bi];
            }
#pragma unroll
        for (int kk = 0; kk < 2; kk++) {
            u32 AHf[2][4], ALf[2][4];
#pragma unroll
            for (int i = 0; i < 2; i++) {
                const __nv_bfloat16* p = Ah + (wm * 32 + i * 16 + g) * ASTR + kk * 16 + tq * 2;
                AHf[i][0] = *(const u32*)p;
                AHf[i][1] = *(const u32*)(p + 8 * ASTR);
                AHf[i][2] = *(const u32*)(p + 8);
                AHf[i][3] = *(const u32*)(p + 8 * ASTR + 8);
                const __nv_bfloat16* q2 = Al + (wm * 32 + i * 16 + g) * ASTR + kk * 16 + tq * 2;
                ALf[i][0] = *(const u32*)q2;
                ALf[i][1] = *(const u32*)(q2 + 8 * ASTR);
                ALf[i][2] = *(const u32*)(q2 + 8);
                ALf[i][3] = *(const u32*)(q2 + 8 * ASTR + 8);
            }
#pragma unroll
            for (int j = 0; j < 4; j++) {
                u32 bh[2] = {BH[kk][j].x, BH[kk][j].y};
                u32 bl[2] = {BL[kk][j].x, BL[kk][j].y};
#pragma unroll
                for (int i = 0; i < 2; i++) {
                    mma_bf16(acc[i][j], AHf[i], bh);
                    mma_bf16(acc[i][j], ALf[i], bh);
                    mma_bf16(acc[i][j], AHf[i], bl);
                }
            }
        }
        __syncthreads();
        if (has_next) {
            *(uint4*)(Ah + asts) = nh;
            *(uint4*)(Al + asts) = nl;
            __syncthreads();
        }
    }

#pragma unroll
    for (int i = 0; i < 2; i++)
#pragma unroll
        for (int j = 0; j < 4; j++) {
            int row = m0 + wm * 32 + i * 16 + g;
            int col = n0 + wn * 32 + j * 8 + tq * 2;
            *(float2*)&xp[(size_t)row * G4 + col] =
                make_float2(acc[i][j][0] + bias[col], acc[i][j][1] + bias[col + 1]);
            *(float2*)&xp[(size_t)(row + 8) * G4 + col] =
                make_float2(acc[i][j][2] + bias[col], acc[i][j][3] + bias[col + 1]);
        }
}

// ---------------- fused recurrent step: pipelined HMMA + gates ----------------
// tile: 64 rows x (4 gates x 32 hc).  grid: [0,160) sc ; [160,320) cm ; [320,352) is
__global__ void __launch_bounds__(256, 2)
step_mma(int t) {
    extern __shared__ char smem[];
    __nv_bfloat16* Ah = (__nv_bfloat16*)smem;
    __nv_bfloat16* Al = Ah + 64 * ASTR;
    float* zs = (float*)smem;   // reused after mainloop: [64][132]

    int bid = blockIdx.x;
    const __nv_bfloat16 *hhin, *hlin;
    __nv_bfloat16 *hhout, *hlout;
    const uint2 *__restrict__ BHp, *__restrict__ BLp;
    float* cst; const float* xp;
    int m0, hc0;

    if (bid < 160) {
        BHp = g_WhhH[0]; BLp = g_WhhL[0];
        hhin = g_hhi_sc[t & 1]; hlin = g_hlo_sc[t & 1];
        hhout = g_hhi_sc[(t + 1) & 1]; hlout = g_hlo_sc[(t + 1) & 1];
        cst = g_c_sc; xp = g_xp_sc + (size_t)t * N_SC * G4;
        m0 = (bid >> 4) * 64; hc0 = (bid & 15) * 32;
    } else if (bid < 320) {
        bid -= 160;
        BHp = g_WhhH[1]; BLp = g_WhhL[1];
        hhin = g_hhi_cm[t & 1]; hlin = g_hlo_cm[t & 1];
        hhout = g_hhi_cm[(t + 1) & 1]; hlout = g_hlo_cm[(t + 1) & 1];
        cst = g_c_cm; xp = g_xp_cm + (size_t)t * N_CM * G4;
        m0 = (bid >> 4) * 64; hc0 = (bid & 15) * 32;
    } else {
        bid -= 320;
        BHp = g_WhhH[2]; BLp = g_WhhL[2];
        hhin = g_hhi_is[t & 1]; hlin = g_hlo_is[t & 1];
        hhout = g_hhi_is[(t + 1) & 1]; hlout = g_hlo_is[(t + 1) & 1];
        cst = g_c_is; xp = g_xp_is + (size_t)t * N_ISP * G4;
        m0 = (bid >> 4) * 64; hc0 = (bid & 15) * 32;
    }

    const int tid = threadIdx.x, lane = tid & 31, warp = tid >> 5;
    const int wm = warp & 1, wn = warp >> 1;
    const int g = lane >> 2, tq = lane & 3;
    const int ar = tid >> 2, aq = tid & 3;
    const u32 asts = (u32)(ar * ASTR + aq * 8);

    float acc[2][4][4];
#pragma unroll
    for (int i = 0; i < 2; i++)
#pragma unroll
        for (int j = 0; j < 4; j++)
#pragma unroll
            for (int q = 0; q < 4; q++) acc[i][j][q] = 0.f;

    {
        size_t off = (size_t)(m0 + ar) * HDIM + aq * 8;
        uint4 vh = *(const uint4*)(hhin + off);
        uint4 vl = *(const uint4*)(hlin + off);
        *(uint4*)(Ah + asts) = vh;
        *(uint4*)(Al + asts) = vl;
    }
    __syncthreads();

#pragma unroll 1
    for (int ch = 0; ch < HDIM / 32; ch++) {
        uint4 nh, nl;
        bool has_next = (ch + 1) < HDIM / 32;
        if (has_next) {
            size_t off = (size_t)(m0 + ar) * HDIM + (ch + 1) * 32 + aq * 8;
            nh = *(const uint4*)(hhin + off);
            nl = *(const uint4*)(hlin + off);
        }
        uint2 BH[2][4], BL[2][4];
#pragma unroll
        for (int kk = 0; kk < 2; kk++)
#pragma unroll
            for (int j = 0; j < 4; j++) {
                int j8 = wn * 64 + (hc0 >> 3) + j;        // gate = wn
                int bi = (j8 * KS_HH + ch * 2 + kk) * 32 + lane;
                BH[kk][j] = BHp[bi];
                BL[kk][j] = BLp[bi];
            }
#pragma unroll
        for (int kk = 0; kk < 2; kk++) {
            u32 AHf[2][4], ALf[2][4];
#pragma unroll
            for (int i = 0; i < 2; i++) {
                const __nv_bfloat16* p = Ah + (wm * 32 + i * 16 + g) * ASTR + kk * 16 + tq * 2;
                AHf[i][0] = *(const u32*)p;
                AHf[i][1] = *(const u32*)(p + 8 * ASTR);
                AHf[i][2] = *(const u32*)(p + 8);
                AHf[i][3] = *(const u32*)(p + 8 * ASTR + 8);
                const __nv_bfloat16* q2 = Al + (wm * 32 + i * 16 + g) * ASTR + kk * 16 + tq * 2;
                ALf[i][0] = *(const u32*)q2;
                ALf[i][1] = *(const u32*)(q2 + 8 * ASTR);
                ALf[i][2] = *(const u32*)(q2 + 8);
                ALf[i][3] = *(const u32*)(q2 + 8 * ASTR + 8);
            }
#pragma unroll
            for (int j = 0; j < 4; j++) {
                u32 bh[2] = {BH[kk][j].x, BH[kk][j].y};
                u32 bl[2] = {BL[kk][j].x, BL[kk][j].y};
#pragma unroll
                for (int i = 0; i < 2; i++) {
                    mma_bf16(acc[i][j], AHf[i], bh);
                    mma_bf16(acc[i][j], ALf[i], bh);
                    mma_bf16(acc[i][j], AHf[i], bl);
                }
            }
        }
        __syncthreads();
        if (has_next) {
            *(uint4*)(Ah + asts) = nh;
            *(uint4*)(Al + asts) = nl;
            __syncthreads();
        }
    }

    // stage z into smem: col = gate*32 + hc_local  (gate = wn)
#pragma unroll
    for (int i = 0; i < 2; i++)
#pragma unroll
        for (int j = 0; j < 4; j++) {
            int row = wm * 32 + i * 16 + g;
            int colz = wn * 32 + j * 8 + tq * 2;
            *(float2*)&zs[row * 132 + colz] = make_float2(acc[i][j][0], acc[i][j][1]);
            *(float2*)&zs[(row + 8) * 132 + colz] = make_float2(acc[i][j][2], acc[i][j][3]);
        }
    __syncthreads();

    // pointwise: r = tid>>2, 8 contiguous hidden cols per thread
    {
        int r = tid >> 2;
        int hcq = (tid & 3) * 8;
        int m = m0 + r;
#pragma unroll
        for (int half = 0; half < 2; half++) {
            int hc = hcq + half * 4;
            int hcg = hc0 + hc;
            const float* zr = zs + r * 132 + hc;
            float4 zi = *(const float4*)(zr);
            float4 zf = *(const float4*)(zr + 32);
            float4 zg = *(const float4*)(zr + 64);
            float4 zo = *(const float4*)(zr + 96);
            const float* xr = xp + (size_t)m * G4 + hcg;
            float4 xi = *(const float4*)(xr);
            float4 xf = *(const float4*)(xr + 512);
            float4 xg = *(const float4*)(xr + 1024);
            float4 xo = *(const float4*)(xr + 1536);
            float vi[4] = {zi.x + xi.x, zi.y + xi.y, zi.z + xi.z, zi.w + xi.w};
            float vf[4] = {zf.x + xf.x, zf.y + xf.y, zf.z + xf.z, zf.w + xf.w};
            float vg[4] = {zg.x + xg.x, zg.y + xg.y, zg.z + xg.z, zg.w + xg.w};
            float vo[4] = {zo.x + xo.x, zo.y + xo.y, zo.z + xo.z, zo.w + xo.w};
            float* cp = cst + (size_t)m * HDIM + hcg;
            float4 cv = *(const float4*)cp;
            float cc[4] = {cv.x, cv.y, cv.z, cv.w};
            float hv[4];
#pragma unroll
            for (int q = 0; q < 4; q++) {
                float ig = sigf(vi[q]), fg = sigf(vf[q]);
                float gg = tanh_f(vg[q]), og = sigf(vo[q]);
                float cn = fg * cc[q] + ig * gg;
                cc[q] = cn;
                hv[q] = og * tanh_f(cn);
            }
            *(float4*)cp = make_float4(cc[0], cc[1], cc[2], cc[3]);
            __nv_bfloat16 h0 = __float2bfloat16(hv[0]), h1 = __float2bfloat16(hv[1]);
            __nv_bfloat16 h2 = __float2bfloat16(hv[2]), h3 = __float2bfloat16(hv[3]);
            __nv_bfloat162* ph = (__nv_bfloat162*)(hhout + (size_t)m * HDIM + hcg);
            ph[0] = __nv_bfloat162(h0, h1); ph[1] = __nv_bfloat162(h2, h3);
            __nv_bfloat162* pl = (__nv_bfloat162*)(hlout + (size_t)m * HDIM + hcg);
            pl[0] = __nv_bfloat162(__float2bfloat16(hv[0] - __bfloat162float(h0)),
                                   __float2bfloat16(hv[1] - __bfloat162float(h1)));
            pl[1] = __nv_bfloat162(__float2bfloat16(hv[2] - __bfloat162float(h2)),
                                   __float2bfloat16(hv[3] - __bfloat162float(h3)));
        }
    }
}

// ---------------- merge & final ----------------
__global__ void merge_kernel(const float* __restrict__ Wmh, const float* __restrict__ bmh,
                             const float* __restrict__ Wmc, const float* __restrict__ bmc)
{
    int wg = (blockIdx.x * blockDim.x + threadIdx.x) >> 5;
    int lane = threadIdx.x & 31;
    if (wg >= 2 * N_SC) return;
    int which = (wg >= N_SC);
    int n = which ? wg - N_SC : wg;
    const float* W = which ? Wmc : Wmh;
    float s = 0.f;
    for (int k = lane; k < HDIM; k += 32) {
        size_t i = (size_t)n * HDIM + k;
        float a, b;
        if (which) { a = g_c_sc[i]; b = g_c_cm[i]; }
        else {
            a = __bfloat162float(g_hhi_sc[0][i]) + __bfloat162float(g_hlo_sc[0][i]);
            b = __bfloat162float(g_hhi_cm[0][i]) + __bfloat162float(g_hlo_cm[0][i]);
        }
        s += a * W[k] + b * W[HDIM + k];
    }
#pragma unroll
    for (int off = 16; off > 0; off >>= 1) s += __shfl_down_sync(0xffffffffu, s, off);
    if (lane == 0) {
        if (which) g_cmm[n] = s + bmc[0];
        else       g_hm[n]  = s + bmh[0];
    }
}

__global__ void final_kernel(const float* __restrict__ Wfh, const float* __restrict__ bfh,
                             const float* __restrict__ Wfc, const float* __restrict__ bfc,
                             float* __restrict__ out)
{
    int gw = (blockIdx.x * blockDim.x + threadIdx.x) >> 5;
    int lane = threadIdx.x & 31;
    if (gw >= 2 * 64 * HDIM) return;
    int which = (gw >= 64 * HDIM);
    int rem = which ? gw - 64 * HDIM : gw;
    int b = rem >> 9, j = rem & 511;
    const float* W  = which ? Wfc : Wfh;
    const float* mv = which ? g_cmm : g_hm;
    const int K = 10 + HDIM;
    float s = 0.f;
    for (int k = lane; k < K; k += 32) {
        float x;
        if (k < 10) x = mv[b * 10 + k];
        else {
            size_t i = (size_t)b * HDIM + (k - 10);
            x = which ? g_c_is[i]
                      : __bfloat162float(g_hhi_is[0][i]) + __bfloat162float(g_hlo_is[0][i]);
        }
        s += W[(size_t)j * K + k] * x;
    }
#pragma unroll
    for (int off = 16; off > 0; off >>= 1) s += __shfl_down_sync(0xffffffffu, s, off);
    if (lane == 0) {
        float bias = which ? bfc[j] : bfh[j];
        out[(size_t)which * 64 * HDIM + (size_t)b * HDIM + j] = s + bias;
    }
}

// ---------------- launch ----------------
extern "C" void kernel_launch(void* const* d_in, const int* in_sizes, int n_in,
                              void* d_out, int out_size)
{
    (void)in_sizes; (void)n_in; (void)out_size;
    const int*   comments = (const int*)  d_in[0];
    const int*   cmids    = (const int*)  d_in[1];
    const int*   issue    = (const int*)  d_in[2];
    const float* emb_sc   = (const float*)d_in[3];
    const float* emb_cm   = (const float*)d_in[4];
    const float* emb_is   = (const float*)d_in[5];
    const float* Wih_sc   = (const float*)d_in[6];
    const float* Whh_sc   = (const float*)d_in[7];
    const float* b_sc     = (const float*)d_in[8];
    const float* Wih_cm   = (const float*)d_in[9];
    const float* Whh_cm   = (const float*)d_in[10];
    const float* b_cm     = (const float*)d_in[11];
    const float* Wih_is   = (const float*)d_in[12];
    const float* Whh_is   = (const float*)d_in[13];
    const float* b_is     = (const float*)d_in[14];
    const float* Wmh      = (const float*)d_in[15];
    const float* bmh      = (const float*)d_in[16];
    const float* Wmc      = (const float*)d_in[17];
    const float* bmc      = (const float*)d_in[18];
    const float* Wfh      = (const float*)d_in[19];
    const float* bfh      = (const float*)d_in[20];
    const float* Wfc      = (const float*)d_in[21];
    const float* bfc      = (const float*)d_in[22];

    zero_state_k<<<(N_SC * HDIM + 255) / 256, 256>>>();
    prep_w<<<(NB_HH + NB_IH + 255) / 256, 256>>>(Whh_sc, Wih_sc, 0);
    prep_w<<<(NB_HH + NB_IH + 255) / 256, 256>>>(Whh_cm, Wih_cm, 1);
    prep_w<<<(NB_HH + NB_IH + 255) / 256, 256>>>(Whh_is, Wih_is, 2);
    prep_embed<<<(int)(((size_t)N_SC * T_SC * 64 + 255) / 256), 256>>>(comments, emb_sc, 0, N_SC, N_SC, T_SC);
    prep_embed<<<(int)(((size_t)N_CM * T_CM * 64 + 255) / 256), 256>>>(cmids, emb_cm, 1, N_CM, N_CM, T_CM);
    prep_embed<<<(int)(((size_t)N_ISP * T_IS * 64 + 255) / 256), 256>>>(issue, emb_is, 2, N_IS_REAL, N_ISP, T_IS);

    xproj_mma<<<dim3(N_SC * T_SC / 64, 16), 256>>>(0, b_sc);
    xproj_mma<<<dim3(N_CM * T_CM / 64, 16), 256>>>(1, b_cm);
    xproj_mma<<<dim3(N_ISP * T_IS / 64, 16), 256>>>(2, b_is);

    for (int t = 0; t < T_SC; t++) {
        int blocks = 160 + ((t < T_CM) ? 160 : 0) + ((t < T_IS) ? 32 : 0);
        step_mma<<<blocks, 256, STEP_SMEM>>>(t);
    }

    merge_kernel<<<(2 * N_SC * 32 + 255) / 256, 256>>>(Wmh, bmh, Wmc, bmc);
    final_kernel<<<(2 * 64 * HDIM * 32 + 255) / 256, 256>>>(Wfh, bfh, Wfc, bfc, (float*)d_out);
}